// round 6
// baseline (speedup 1.0000x reference)
#include <cuda_runtime.h>

// Problem constants
#define BATCH 16
#define H 1080
#define W 1920
#define OH (H - 6)   // 1074
#define OW (W - 6)   // 1914

// Tiling: 128 threads/CTA, each thread owns NC=4 output columns, streams TH rows.
#define NTHREADS 128
#define NC 4
#define TW (NTHREADS * NC)  // 512 output cols per CTA
#define TH 50
#define RH 56               // TH+6, even multiple of 7 (2-row pipeline + ring of 7)
#define TILESX 4            // 4*512 = 2048 >= 1914
#define TILESY 22           // 22*50 = 1100 >= 1074
#define NBLOCKS (BATCH * TILESX * TILESY)  // 1408

#define C1_CONST 6.5025f    // (0.01*255)^2
#define C2_CONST 58.5225f   // (0.03*255)^2

typedef unsigned long long u64;

__device__ float g_part[NBLOCKS];
__device__ unsigned int g_count = 0;

// ---- f32x2 packed helpers (sm_103a) ----
__device__ __forceinline__ u64 pk(float lo, float hi) {
    u64 r; asm("mov.b64 %0, {%1, %2};" : "=l"(r) : "f"(lo), "f"(hi)); return r;
}
__device__ __forceinline__ void unpk(float& lo, float& hi, u64 v) {
    asm("mov.b64 {%0, %1}, %2;" : "=f"(lo), "=f"(hi) : "l"(v));
}
__device__ __forceinline__ u64 add2(u64 a, u64 b) {
    u64 r; asm("add.rn.f32x2 %0, %1, %2;" : "=l"(r) : "l"(a), "l"(b)); return r;
}
__device__ __forceinline__ u64 sub2(u64 a, u64 b) {
    u64 r; asm("sub.rn.f32x2 %0, %1, %2;" : "=l"(r) : "l"(a), "l"(b)); return r;
}
__device__ __forceinline__ u64 mul2(u64 a, u64 b) {
    u64 r; asm("mul.rn.f32x2 %0, %1, %2;" : "=l"(r) : "l"(a), "l"(b)); return r;
}

struct RowBuf { float4 a0, a1, a2, b0, b1, b2; };

__global__ __launch_bounds__(NTHREADS, 3) void ssim_kernel(
    const float* __restrict__ img1,
    const float* __restrict__ img2,
    const float* __restrict__ window,
    float* __restrict__ out)
{
    // Dynamic smem rings: per-thread private slots (no barriers needed).
    extern __shared__ u64 dynsmem[];
    u64*   ringAB = dynsmem;                          // [7][128][4] u64 {s1,s2}
    u64*   ringSQ = dynsmem + 7 * NTHREADS * 4;       // [7][128][4] u64 {s11,s22}
    float* ring12 = (float*)(dynsmem + 14 * NTHREADS * 4); // [7][128][4] f32 s12
    __shared__ float  red[NTHREADS / 32];
    __shared__ double redd[NTHREADS / 32];
    __shared__ bool   is_last;

    const int bid = blockIdx.x;
    const int batch = bid / (TILESX * TILESY);
    const int tidx = bid % (TILESX * TILESY);
    const int tx0 = (tidx % TILESX) * TW;
    const int ty0 = (tidx / TILESX) * TH;

    const float* __restrict__ p1 = img1 + (size_t)batch * (H * W);
    const float* __restrict__ p2 = img2 + (size_t)batch * (H * W);

    const int t = threadIdx.x;
    const int c0 = tx0 + t * NC;               // first output col of this thread
    // Clamped, 16B-aligned load offsets (clamped data only feeds invalid cols).
    const int l0 = (c0     < W - 4) ? c0     : (W - 4);
    const int l1 = (c0 + 4 < W - 4) ? c0 + 4 : (W - 4);
    const int l2 = (c0 + 8 < W - 4) ? c0 + 8 : (W - 4);
    const bool ok0 = (c0     < OW);
    const bool ok1 = (c0 + 1 < OW);
    const bool ok2 = (c0 + 2 < OW);
    const bool ok3 = (c0 + 3 < OW);
    const float inv = window[0];               // 1/49

    // Zero this thread's ring slots.
    #pragma unroll
    for (int j = 0; j < 7; j++) {
        const int sb = (j * NTHREADS + t) * 4;
        ((ulonglong2*)(ringAB + sb))[0] = make_ulonglong2(0ull, 0ull);
        ((ulonglong2*)(ringAB + sb))[1] = make_ulonglong2(0ull, 0ull);
        ((ulonglong2*)(ringSQ + sb))[0] = make_ulonglong2(0ull, 0ull);
        ((ulonglong2*)(ringSQ + sb))[1] = make_ulonglong2(0ull, 0ull);
        *((float4*)(ring12 + sb)) = make_float4(0.f, 0.f, 0.f, 0.f);
    }

    // Vertical running window sums per owned column (f32x2 packs {img1,img2}).
    u64 vab0 = 0, vab1 = 0, vab2 = 0, vab3 = 0;
    u64 vsq0 = 0, vsq1 = 0, vsq2 = 0, vsq3 = 0;
    float v12_0 = 0.f, v12_1 = 0.f, v12_2 = 0.f, v12_3 = 0.f;
    float acc = 0.f;

    auto loadrow = [&](int r, RowBuf& B) {
        int gy = ty0 + r; if (gy > H - 1) gy = H - 1;
        const float* __restrict__ r1 = p1 + (size_t)gy * W;
        const float* __restrict__ r2 = p2 + (size_t)gy * W;
        B.a0 = *(const float4*)(r1 + l0);
        B.a1 = *(const float4*)(r1 + l1);
        B.a2 = *(const float4*)(r1 + l2);
        B.b0 = *(const float4*)(r2 + l0);
        B.b1 = *(const float4*)(r2 + l1);
        B.b2 = *(const float4*)(r2 + l2);
    };

    auto process = [&](const RowBuf& B, int r, int j) {
        const float ax[12] = {B.a0.x, B.a0.y, B.a0.z, B.a0.w,
                              B.a1.x, B.a1.y, B.a1.z, B.a1.w,
                              B.a2.x, B.a2.y, B.a2.z, B.a2.w};
        const float bx[12] = {B.b0.x, B.b0.y, B.b0.z, B.b0.w,
                              B.b1.x, B.b1.y, B.b1.z, B.b1.w,
                              B.b2.x, B.b2.y, B.b2.z, B.b2.w};
        u64 ab[10], sq[10];
        float p12[10];
        #pragma unroll
        for (int k = 0; k < 10; k++) {
            ab[k] = pk(ax[k], bx[k]);
            sq[k] = mul2(ab[k], ab[k]);
            p12[k] = ax[k] * bx[k];
        }
        // Horizontal 7-window sums, x-sliding across the 4 owned columns.
        u64 wab0 = add2(add2(add2(ab[0], ab[1]), add2(ab[2], ab[3])),
                        add2(add2(ab[4], ab[5]), ab[6]));
        u64 wab1 = add2(wab0, sub2(ab[7], ab[0]));
        u64 wab2 = add2(wab1, sub2(ab[8], ab[1]));
        u64 wab3 = add2(wab2, sub2(ab[9], ab[2]));
        u64 wsq0 = add2(add2(add2(sq[0], sq[1]), add2(sq[2], sq[3])),
                        add2(add2(sq[4], sq[5]), sq[6]));
        u64 wsq1 = add2(wsq0, sub2(sq[7], sq[0]));
        u64 wsq2 = add2(wsq1, sub2(sq[8], sq[1]));
        u64 wsq3 = add2(wsq2, sub2(sq[9], sq[2]));
        float wp0 = ((p12[0] + p12[1]) + (p12[2] + p12[3])) +
                    ((p12[4] + p12[5]) + p12[6]);
        float wp1 = wp0 + (p12[7] - p12[0]);
        float wp2 = wp1 + (p12[8] - p12[1]);
        float wp3 = wp2 + (p12[9] - p12[2]);

        // Ring exchange (drop row r-7 sums, store row r sums).
        const int sb = (j * NTHREADS + t) * 4;
        ulonglong2* rab = (ulonglong2*)(ringAB + sb);
        ulonglong2* rsq = (ulonglong2*)(ringSQ + sb);
        float4*     r12 = (float4*)(ring12 + sb);
        ulonglong2 oabA = rab[0], oabB = rab[1];
        ulonglong2 osqA = rsq[0], osqB = rsq[1];
        float4     o12  = r12[0];

        vab0 = add2(vab0, sub2(wab0, oabA.x));
        vab1 = add2(vab1, sub2(wab1, oabA.y));
        vab2 = add2(vab2, sub2(wab2, oabB.x));
        vab3 = add2(vab3, sub2(wab3, oabB.y));
        vsq0 = add2(vsq0, sub2(wsq0, osqA.x));
        vsq1 = add2(vsq1, sub2(wsq1, osqA.y));
        vsq2 = add2(vsq2, sub2(wsq2, osqB.x));
        vsq3 = add2(vsq3, sub2(wsq3, osqB.y));
        v12_0 += wp0 - o12.x;
        v12_1 += wp1 - o12.y;
        v12_2 += wp2 - o12.z;
        v12_3 += wp3 - o12.w;

        rab[0] = make_ulonglong2(wab0, wab1);
        rab[1] = make_ulonglong2(wab2, wab3);
        rsq[0] = make_ulonglong2(wsq0, wsq1);
        rsq[1] = make_ulonglong2(wsq2, wsq3);
        r12[0] = make_float4(wp0, wp1, wp2, wp3);

        if (r >= 6) {
            const int oy = ty0 + r - 6;
            if (oy < OH) {
                u64 vabs[4] = {vab0, vab1, vab2, vab3};
                u64 vsqs[4] = {vsq0, vsq1, vsq2, vsq3};
                float v12s[4] = {v12_0, v12_1, v12_2, v12_3};
                bool oks[4] = {ok0, ok1, ok2, ok3};
                #pragma unroll
                for (int i = 0; i < 4; i++) {
                    if (oks[i]) {
                        float V1, V2, V11, V22;
                        unpk(V1, V2, vabs[i]);
                        unpk(V11, V22, vsqs[i]);
                        float mu1 = V1 * inv, mu2 = V2 * inv;
                        float mu1s = mu1 * mu1, mu2s = mu2 * mu2, mu12 = mu1 * mu2;
                        float sig1 = V11 * inv - mu1s;
                        float sig2 = V22 * inv - mu2s;
                        float sg12 = v12s[i] * inv - mu12;
                        float num = (2.f * mu12 + C1_CONST) * (2.f * sg12 + C2_CONST);
                        float den = (mu1s + mu2s + C1_CONST) * (sig1 + sig2 + C2_CONST);
                        acc += __fdividef(num, den);
                    }
                }
            }
        }
    };

    // Software-pipelined mainloop: 2 rows per iteration, loads lead by 1-2 rows.
    RowBuf A, Bf;
    loadrow(0, A);
    int jA = 0;
    for (int rp = 0; rp < RH; rp += 2) {
        const int jB = (jA == 6) ? 0 : jA + 1;
        loadrow(rp + 1, Bf);
        process(A, rp, jA);
        loadrow(rp + 2, A);
        process(Bf, rp + 1, jB);
        jA += 2; if (jA >= 7) jA -= 7;
    }

    // Block reduction (128 -> 4 -> 1).
    int lane = t & 31;
    int warp = t >> 5;
    #pragma unroll
    for (int off = 16; off; off >>= 1)
        acc += __shfl_down_sync(0xffffffff, acc, off);
    if (lane == 0) red[warp] = acc;
    __syncthreads();
    float blockAcc = 0.f;
    if (warp == 0) {
        float v = (lane < NTHREADS / 32) ? red[lane] : 0.f;
        #pragma unroll
        for (int off = 2; off; off >>= 1)
            v += __shfl_down_sync(0xffffffff, v, off);
        blockAcc = v;
    }

    // Last-block final reduction.
    if (t == 0) {
        g_part[bid] = blockAcc;
        __threadfence();
        unsigned int prev = atomicAdd(&g_count, 1u);
        is_last = (prev == (unsigned int)(gridDim.x - 1));
    }
    __syncthreads();

    if (is_last) {
        double s = 0.0;
        for (int i = t; i < NBLOCKS; i += NTHREADS)
            s += (double)g_part[i];
        #pragma unroll
        for (int off = 16; off; off >>= 1)
            s += __shfl_down_sync(0xffffffff, s, off);
        if (lane == 0) redd[warp] = s;
        __syncthreads();
        if (warp == 0) {
            double v = (lane < NTHREADS / 32) ? redd[lane] : 0.0;
            #pragma unroll
            for (int off = 2; off; off >>= 1)
                v += __shfl_down_sync(0xffffffff, v, off);
            if (lane == 0) {
                out[0] = (float)(v / ((double)BATCH * OH * OW));
                g_count = 0;  // self-reset for next graph replay
            }
        }
    }
}

extern "C" void kernel_launch(void* const* d_in, const int* in_sizes, int n_in,
                              void* d_out, int out_size) {
    const float* img1 = (const float*)d_in[0];
    const float* img2 = (const float*)d_in[1];
    const float* window = (const float*)d_in[2];
    float* out = (float*)d_out;

    const int smem_bytes = (14 * NTHREADS * 4) * 8 + (7 * NTHREADS * 4) * 4; // 71680
    cudaFuncSetAttribute(ssim_kernel, cudaFuncAttributeMaxDynamicSharedMemorySize,
                         smem_bytes);
    ssim_kernel<<<NBLOCKS, NTHREADS, smem_bytes>>>(img1, img2, window, out);
}

// round 7
// speedup vs baseline: 1.5598x; 1.5598x over previous
#include <cuda_runtime.h>

// Problem constants
#define BATCH 16
#define H 1080
#define W 1920
#define OH (H - 6)   // 1074
#define OW (W - 6)   // 1914

// Tiling: 128 threads/CTA, each thread owns NC=2 output columns, streams TH rows.
#define NTHREADS 128
#define NC 2
#define TW (NTHREADS * NC)  // 256 output cols per CTA
#define TH 64
#define RH 70               // TH+6, even, multiple of 7
#define TILESX 8            // 8*256 = 2048 >= 1914
#define TILESY 17           // 17*64 = 1088 >= 1074
#define NBLOCKS (BATCH * TILESX * TILESY)  // 2176

#define C1_CONST 6.5025f    // (0.01*255)^2
#define C2_CONST 58.5225f   // (0.03*255)^2

__device__ float g_part[NBLOCKS];
__device__ unsigned int g_count = 0;

struct RowBuf { float2 a0, a1, a2, a3, b0, b1, b2, b3; };  // cols c0..c0+7, both imgs

__global__ __launch_bounds__(NTHREADS, 6) void ssim_kernel(
    const float* __restrict__ img1,
    const float* __restrict__ img2,
    const float* __restrict__ window,
    float* __restrict__ out)
{
    // Ring buffers: per-thread private slots, [quantity][7][tid] as float2 {w0,w1}.
    // 5 * 7 * 128 * 8B = 35840 B -> 6 CTAs/SM.
    extern __shared__ float2 ring[];
    float2* const ringS1  = ring;                  // sum a
    float2* const ringS2  = ring + 1 * 7 * NTHREADS;
    float2* const ringS11 = ring + 2 * 7 * NTHREADS;
    float2* const ringS22 = ring + 3 * 7 * NTHREADS;
    float2* const ringS12 = ring + 4 * 7 * NTHREADS;
    __shared__ float  red[NTHREADS / 32];
    __shared__ double redd[NTHREADS / 32];
    __shared__ bool   is_last;

    const int bid = blockIdx.x;
    const int batch = bid / (TILESX * TILESY);
    const int tidx = bid % (TILESX * TILESY);
    const int tx0 = (tidx % TILESX) * TW;
    const int ty0 = (tidx / TILESX) * TH;

    const float* __restrict__ p1 = img1 + (size_t)batch * (H * W);
    const float* __restrict__ p2 = img2 + (size_t)batch * (H * W);

    const int t = threadIdx.x;
    const int c0 = tx0 + t * NC;                 // first output col (even)
    const int ce = (c0 <= W - 8) ? c0 : (W - 8); // clamped 8-col read base (even)
    const bool ok0 = (c0     < OW);
    const bool ok1 = (c0 + 1 < OW);
    const float inv = window[0];                 // 1/49

    // Zero this thread's ring slots.
    #pragma unroll
    for (int j = 0; j < 7; j++) {
        const int s = j * NTHREADS + t;
        ringS1[s] = make_float2(0.f, 0.f);
        ringS2[s] = make_float2(0.f, 0.f);
        ringS11[s] = make_float2(0.f, 0.f);
        ringS22[s] = make_float2(0.f, 0.f);
        ringS12[s] = make_float2(0.f, 0.f);
    }

    // Vertical running 7-row window sums for the 2 owned columns.
    float v1x = 0.f, v1y = 0.f, v2x = 0.f, v2y = 0.f;
    float v11x = 0.f, v11y = 0.f, v22x = 0.f, v22y = 0.f;
    float v12x = 0.f, v12y = 0.f;
    float acc = 0.f;

    auto loadrow = [&](int r, RowBuf& B) {
        int gy = ty0 + r; if (gy > H - 1) gy = H - 1;
        const float* __restrict__ r1 = p1 + (size_t)gy * W + ce;
        const float* __restrict__ r2 = p2 + (size_t)gy * W + ce;
        B.a0 = *(const float2*)(r1);     B.a1 = *(const float2*)(r1 + 2);
        B.a2 = *(const float2*)(r1 + 4); B.a3 = *(const float2*)(r1 + 6);
        B.b0 = *(const float2*)(r2);     B.b1 = *(const float2*)(r2 + 2);
        B.b2 = *(const float2*)(r2 + 4); B.b3 = *(const float2*)(r2 + 6);
    };

    auto process = [&](const RowBuf& B, int r, int j) {
        const float a0 = B.a0.x, a1 = B.a0.y, a2 = B.a1.x, a3 = B.a1.y;
        const float a4 = B.a2.x, a5 = B.a2.y, a6 = B.a3.x, a7 = B.a3.y;
        const float b0 = B.b0.x, b1 = B.b0.y, b2 = B.b1.x, b3 = B.b1.y;
        const float b4 = B.b2.x, b5 = B.b2.y, b6 = B.b3.x, b7 = B.b3.y;

        // Horizontal 7-window sums for output cols c0, c0+1 via shared core k1..k6.
        float c;
        c = ((a1 + a2) + (a3 + a4)) + (a5 + a6);
        const float w1x = c + a0, w1y = c + a7;
        c = ((b1 + b2) + (b3 + b4)) + (b5 + b6);
        const float w2x = c + b0, w2y = c + b7;

        const float qa0 = a0*a0, qa1 = a1*a1, qa2 = a2*a2, qa3 = a3*a3;
        const float qa4 = a4*a4, qa5 = a5*a5, qa6 = a6*a6, qa7 = a7*a7;
        c = ((qa1 + qa2) + (qa3 + qa4)) + (qa5 + qa6);
        const float w11x = c + qa0, w11y = c + qa7;

        const float qb0 = b0*b0, qb1 = b1*b1, qb2 = b2*b2, qb3 = b3*b3;
        const float qb4 = b4*b4, qb5 = b5*b5, qb6 = b6*b6, qb7 = b7*b7;
        c = ((qb1 + qb2) + (qb3 + qb4)) + (qb5 + qb6);
        const float w22x = c + qb0, w22y = c + qb7;

        const float p0 = a0*b0, p1 = a1*b1, p2 = a2*b2, p3 = a3*b3;
        const float p4 = a4*b4, p5 = a5*b5, p6 = a6*b6, p7 = a7*b7;
        c = ((p1 + p2) + (p3 + p4)) + (p5 + p6);
        const float w12x = c + p0, w12y = c + p7;

        // Ring exchange + vertical sliding window.
        const int s = j * NTHREADS + t;
        const float2 o1 = ringS1[s], o2 = ringS2[s];
        const float2 o11 = ringS11[s], o22 = ringS22[s], o12 = ringS12[s];
        v1x  += w1x  - o1.x;   v1y  += w1y  - o1.y;
        v2x  += w2x  - o2.x;   v2y  += w2y  - o2.y;
        v11x += w11x - o11.x;  v11y += w11y - o11.y;
        v22x += w22x - o22.x;  v22y += w22y - o22.y;
        v12x += w12x - o12.x;  v12y += w12y - o12.y;
        ringS1[s]  = make_float2(w1x, w1y);
        ringS2[s]  = make_float2(w2x, w2y);
        ringS11[s] = make_float2(w11x, w11y);
        ringS22[s] = make_float2(w22x, w22y);
        ringS12[s] = make_float2(w12x, w12y);

        if (r >= 6) {
            const int oy = ty0 + r - 6;
            if (oy < OH) {
                if (ok0) {
                    const float mu1 = v1x * inv, mu2 = v2x * inv;
                    const float mu1s = mu1*mu1, mu2s = mu2*mu2, mu12 = mu1*mu2;
                    const float sig1 = fmaf(v11x, inv, -mu1s);
                    const float sig2 = fmaf(v22x, inv, -mu2s);
                    const float sg12 = fmaf(v12x, inv, -mu12);
                    const float num = fmaf(mu12, 2.f, C1_CONST) * fmaf(sg12, 2.f, C2_CONST);
                    const float den = (mu1s + mu2s + C1_CONST) * (sig1 + sig2 + C2_CONST);
                    acc += __fdividef(num, den);
                }
                if (ok1) {
                    const float mu1 = v1y * inv, mu2 = v2y * inv;
                    const float mu1s = mu1*mu1, mu2s = mu2*mu2, mu12 = mu1*mu2;
                    const float sig1 = fmaf(v11y, inv, -mu1s);
                    const float sig2 = fmaf(v22y, inv, -mu2s);
                    const float sg12 = fmaf(v12y, inv, -mu12);
                    const float num = fmaf(mu12, 2.f, C1_CONST) * fmaf(sg12, 2.f, C2_CONST);
                    const float den = (mu1s + mu2s + C1_CONST) * (sig1 + sig2 + C2_CONST);
                    acc += __fdividef(num, den);
                }
            }
        }
    };

    // 2-row software pipeline (loads lead compute by 1-2 rows).
    RowBuf A, Bf;
    loadrow(0, A);
    int jA = 0;
    for (int rp = 0; rp < RH; rp += 2) {
        const int jB = (jA == 6) ? 0 : jA + 1;
        loadrow(rp + 1, Bf);
        process(A, rp, jA);
        loadrow(rp + 2, A);          // rp+2 == RH on last iter: clamped, discarded
        process(Bf, rp + 1, jB);
        jA += 2; if (jA >= 7) jA -= 7;
    }

    // Block reduction (128 -> 4 -> 1).
    const int lane = t & 31;
    const int warp = t >> 5;
    #pragma unroll
    for (int off = 16; off; off >>= 1)
        acc += __shfl_down_sync(0xffffffff, acc, off);
    if (lane == 0) red[warp] = acc;
    __syncthreads();
    float blockAcc = 0.f;
    if (warp == 0) {
        float v = (lane < NTHREADS / 32) ? red[lane] : 0.f;
        #pragma unroll
        for (int off = 2; off; off >>= 1)
            v += __shfl_down_sync(0xffffffff, v, off);
        blockAcc = v;
    }

    // Last-block final reduction.
    if (t == 0) {
        g_part[bid] = blockAcc;
        __threadfence();
        unsigned int prev = atomicAdd(&g_count, 1u);
        is_last = (prev == (unsigned int)(gridDim.x - 1));
    }
    __syncthreads();

    if (is_last) {
        double s = 0.0;
        for (int i = t; i < NBLOCKS; i += NTHREADS)
            s += (double)g_part[i];
        #pragma unroll
        for (int off = 16; off; off >>= 1)
            s += __shfl_down_sync(0xffffffff, s, off);
        if (lane == 0) redd[warp] = s;
        __syncthreads();
        if (warp == 0) {
            double v = (lane < NTHREADS / 32) ? redd[lane] : 0.0;
            #pragma unroll
            for (int off = 2; off; off >>= 1)
                v += __shfl_down_sync(0xffffffff, v, off);
            if (lane == 0) {
                out[0] = (float)(v / ((double)BATCH * OH * OW));
                g_count = 0;  // self-reset for next graph replay
            }
        }
    }
}

extern "C" void kernel_launch(void* const* d_in, const int* in_sizes, int n_in,
                              void* d_out, int out_size) {
    const float* img1 = (const float*)d_in[0];
    const float* img2 = (const float*)d_in[1];
    const float* window = (const float*)d_in[2];
    float* out = (float*)d_out;

    const int smem_bytes = 5 * 7 * NTHREADS * (int)sizeof(float2);  // 35840
    ssim_kernel<<<NBLOCKS, NTHREADS, smem_bytes>>>(img1, img2, window, out);
}